// round 1
// baseline (speedup 1.0000x reference)
#include <cuda_runtime.h>

typedef unsigned long long ull;

#define LOG2E 1.4426950408889634f
#define BB 32
#define NN 512
#define NH 8
#define ND 8
#define NF 128

// ---------------- scratch (static device globals; no allocation) ----------------
__device__ float g_Wh1[BB * NH * NN * ND];   // layer-1 projected features, [b][h][n][d]
__device__ float g_x[BB * NN * NH * ND];     // layer-1 output (concat heads), [b][n][h*8+d]
__device__ float g_Wh2[BB * NN * ND];        // layer-2 projected, [b][n][d]
__device__ float g_s1[BB * NN];              // layer-2 s1 (pre-scaled by log2e)
__device__ float g_s2[BB * NN];              // layer-2 s2 (pre-scaled by log2e)
__device__ float g_h0p[BB][4][ND];           // layer-2 per-chunk partial sums for node 0

// ---------------- helpers ----------------
__device__ __forceinline__ float ex2f(float x) {
    float r; asm("ex2.approx.f32 %0, %1;" : "=f"(r) : "f"(x)); return r;
}
__device__ __forceinline__ void ffma2(ull &acc, ull a, ull b) {
    asm("fma.rn.f32x2 %0, %1, %2, %0;" : "+l"(acc) : "l"(a), "l"(b));
}
__device__ __forceinline__ ull pack2(float x) {
    ull r; asm("mov.b64 %0, {%1, %1};" : "=l"(r) : "f"(x)); return r;
}
__device__ __forceinline__ float lrelu02(float x) { return fmaxf(x, 0.2f * x); }
__device__ __forceinline__ float eluf(float x) { return x > 0.f ? x : expm1f(x); }

// =====================================================================
// K1: Wh1[b,h,n,d] = sum_f nf[b,n,f] * Ws[h,f,d]   (all 64 outputs per n)
// grid (32, 4), 256 threads: 128 n-rows per block, 2 threads per row
// =====================================================================
__global__ __launch_bounds__(256) void k1_proj(const float* __restrict__ nf,
                                               const float* __restrict__ Ws) {
    __shared__ ull Wsm[128][32];             // Wsm[f][c2] packs cols (2c2, 2c2+1); c = h*8+d
    const int b = blockIdx.x, tid = threadIdx.x;
    float* Wf = reinterpret_cast<float*>(Wsm);
    for (int idx = tid; idx < 128 * 64; idx += 256) {
        int f = idx >> 6, c = idx & 63;
        Wf[idx] = Ws[((c >> 3) * 128 + f) * 8 + (c & 7)];
    }
    __syncthreads();

    const int nl = tid & 127, q = tid >> 7;
    const int n = blockIdx.y * 128 + nl;
    const float4* row = reinterpret_cast<const float4*>(nf + (b * NN + n) * NF);

    ull acc[16];
#pragma unroll
    for (int k = 0; k < 16; k++) acc[k] = 0ull;

#pragma unroll 4
    for (int f4 = 0; f4 < 32; f4++) {
        float4 v = row[f4];
        float vs[4] = {v.x, v.y, v.z, v.w};
#pragma unroll
        for (int u = 0; u < 4; u++) {
            ull p = pack2(vs[u]);
            const ull* wrow = &Wsm[f4 * 4 + u][q * 16];
#pragma unroll
            for (int k = 0; k < 16; k++) ffma2(acc[k], p, wrow[k]);
        }
    }

    ull* out = reinterpret_cast<ull*>(g_Wh1);
#pragma unroll
    for (int k = 0; k < 16; k++) {
        int c0 = q * 32 + 2 * k;
        int h = c0 >> 3, d = c0 & 7;
        out[((size_t)(b * NH + h) * NN + n) * 4 + (d >> 1)] = acc[k];
    }
}

// =====================================================================
// K2: layer-1 attention per (b, h). softmax over axis=1 (normalize over i):
//   Z_j = sum_i exp(lrelu(s1_i + s2_j));  h1[i,d] = sum_j exp(..)_ij/Z_j * Wh[j,d]
// grid (32, 8), 512 threads
// =====================================================================
__global__ __launch_bounds__(512) void k2_att1(const float* __restrict__ As) {
    __shared__ float whs[NN * ND];
    __shared__ float s1s[NN];
    __shared__ float s2s[NN];
    __shared__ float mjs[NN];
    __shared__ float redbuf[16];

    const int b = blockIdx.x, h = blockIdx.y, tid = threadIdx.x;
    const float* wg = g_Wh1 + (size_t)(b * NH + h) * NN * ND;

    float4 w0 = reinterpret_cast<const float4*>(wg)[tid * 2];
    float4 w1 = reinterpret_cast<const float4*>(wg)[tid * 2 + 1];
    reinterpret_cast<float4*>(whs)[tid * 2] = w0;
    reinterpret_cast<float4*>(whs)[tid * 2 + 1] = w1;

    const float* a = As + h * 16;
    float s1 = w0.x * a[0] + w0.y * a[1] + w0.z * a[2] + w0.w * a[3]
             + w1.x * a[4] + w1.y * a[5] + w1.z * a[6] + w1.w * a[7];
    float s2 = w0.x * a[8] + w0.y * a[9] + w0.z * a[10] + w0.w * a[11]
             + w1.x * a[12] + w1.y * a[13] + w1.z * a[14] + w1.w * a[15];
    float s1L = s1 * LOG2E, s2L = s2 * LOG2E;
    s1s[tid] = s1L;
    s2s[tid] = s2L;

    // block max of s1L (for overflow-safe softmax; cancels exactly in the ratio)
    float m = s1L;
#pragma unroll
    for (int o = 16; o >= 1; o >>= 1) m = fmaxf(m, __shfl_xor_sync(0xffffffffu, m, o));
    if ((tid & 31) == 0) redbuf[tid >> 5] = m;
    __syncthreads();
    float maxs1 = redbuf[0];
#pragma unroll
    for (int w = 1; w < 16; w++) maxs1 = fmaxf(maxs1, redbuf[w]);

    // ---- pass 1: thread j computes Z_j, then scales its Wh row by 1/Z_j ----
    const float s2j = s2s[tid];
    const float mj = lrelu02(maxs1 + s2j);
    float Z = 0.f;
#pragma unroll 8
    for (int i = 0; i < NN; i++) Z += ex2f(lrelu02(s1s[i] + s2j) - mj);
    mjs[tid] = mj;
    const float rz = 1.0f / Z;
#pragma unroll
    for (int d = 0; d < 8; d++) whs[tid * 8 + d] *= rz;
    __syncthreads();

    // ---- pass 2: thread i accumulates h1[i, 0..7] with packed f32x2 FMA ----
    const float s1i = s1s[tid];
    ull acc0 = 0, acc1 = 0, acc2 = 0, acc3 = 0;
    const ull* whp = reinterpret_cast<const ull*>(whs);
#pragma unroll 4
    for (int j = 0; j < NN; j++) {
        float e = ex2f(lrelu02(s1i + s2s[j]) - mjs[j]);
        ull ep = pack2(e);
        const ull* wr = whp + j * 4;
        ffma2(acc0, ep, wr[0]);
        ffma2(acc1, ep, wr[1]);
        ffma2(acc2, ep, wr[2]);
        ffma2(acc3, ep, wr[3]);
    }

    ull accs[4] = {acc0, acc1, acc2, acc3};
    float r[8];
#pragma unroll
    for (int k = 0; k < 4; k++) {
        r[2 * k]     = eluf(__uint_as_float((unsigned)(accs[k] & 0xffffffffu)));
        r[2 * k + 1] = eluf(__uint_as_float((unsigned)(accs[k] >> 32)));
    }
    float4* xo = reinterpret_cast<float4*>(g_x + (size_t)(b * NN + tid) * (NH * ND) + h * ND);
    xo[0] = make_float4(r[0], r[1], r[2], r[3]);
    xo[1] = make_float4(r[4], r[5], r[6], r[7]);
}

// =====================================================================
// K3: layer-2 projection: Wh2[b,n,:] = x[b,n,:] @ W_out (64x8); s1,s2 via a_out
// grid (32, 2), 256 threads
// =====================================================================
__global__ __launch_bounds__(256) void k3_proj2(const float* __restrict__ Wout,
                                                const float* __restrict__ aout) {
    __shared__ float Wo[64 * 8];
    __shared__ float ao[16];
    const int b = blockIdx.x, tid = threadIdx.x;
    const int n = blockIdx.y * 256 + tid;
    for (int idx = tid; idx < 512; idx += 256) Wo[idx] = Wout[idx];
    if (tid < 16) ao[tid] = aout[tid];
    __syncthreads();

    const float4* row = reinterpret_cast<const float4*>(g_x + (size_t)(b * NN + n) * 64);
    float acc[8] = {0, 0, 0, 0, 0, 0, 0, 0};
#pragma unroll 4
    for (int f4 = 0; f4 < 16; f4++) {
        float4 v = row[f4];
        float vs[4] = {v.x, v.y, v.z, v.w};
#pragma unroll
        for (int u = 0; u < 4; u++) {
            const float* wr = &Wo[(f4 * 4 + u) * 8];
#pragma unroll
            for (int d = 0; d < 8; d++) acc[d] += vs[u] * wr[d];
        }
    }
    float s1 = 0.f, s2 = 0.f;
#pragma unroll
    for (int d = 0; d < 8; d++) { s1 += acc[d] * ao[d]; s2 += acc[d] * ao[8 + d]; }
    g_s1[b * NN + n] = s1 * LOG2E;
    g_s2[b * NN + n] = s2 * LOG2E;
    float4* o = reinterpret_cast<float4*>(g_Wh2 + (size_t)(b * NN + n) * 8);
    o[0] = make_float4(acc[0], acc[1], acc[2], acc[3]);
    o[1] = make_float4(acc[4], acc[5], acc[6], acc[7]);
}

// =====================================================================
// K4: layer-2 attention, output row i=0 only.
//   w_j = exp(lrelu(s1_0+s2_j)) / sum_i exp(lrelu(s1_i+s2_j)); h0[d] = sum_j w_j*Wh2[j,d]
// grid (32, 4) [j-chunks of 128], 512 threads: 4 threads per j split the i-sum
// =====================================================================
__global__ __launch_bounds__(512) void k4_att2() {
    __shared__ float s1s[NN];
    __shared__ float s2s[NN];
    __shared__ float redbuf[16];
    __shared__ float wpart[16][8];

    const int b = blockIdx.x, jc = blockIdx.y, tid = threadIdx.x;
    s1s[tid] = g_s1[b * NN + tid];
    s2s[tid] = g_s2[b * NN + tid];

    float m = s1s[tid];
#pragma unroll
    for (int o = 16; o >= 1; o >>= 1) m = fmaxf(m, __shfl_xor_sync(0xffffffffu, m, o));
    if ((tid & 31) == 0) redbuf[tid >> 5] = m;
    __syncthreads();
    float maxs1 = redbuf[0];
#pragma unroll
    for (int w = 1; w < 16; w++) maxs1 = fmaxf(maxs1, redbuf[w]);

    const int jl = tid >> 2, iq = tid & 3;
    const int j = jc * 128 + jl;
    const float s2j = s2s[j];
    const float mj = lrelu02(maxs1 + s2j);

    float Zp = 0.f;
#pragma unroll 8
    for (int i = iq; i < NN; i += 4) Zp += ex2f(lrelu02(s1s[i] + s2j) - mj);
    Zp += __shfl_xor_sync(0xffffffffu, Zp, 1);
    Zp += __shfl_xor_sync(0xffffffffu, Zp, 2);

    const float num = ex2f(lrelu02(s1s[0] + s2j) - mj);
    const float wj = (iq == 0) ? num / Zp : 0.f;

    const float* w2 = g_Wh2 + (size_t)(b * NN + j) * 8;
    float p[8];
#pragma unroll
    for (int d = 0; d < 8; d++) p[d] = wj * w2[d];
#pragma unroll
    for (int d = 0; d < 8; d++) {
        p[d] += __shfl_xor_sync(0xffffffffu, p[d], 4);
        p[d] += __shfl_xor_sync(0xffffffffu, p[d], 8);
        p[d] += __shfl_xor_sync(0xffffffffu, p[d], 16);
    }
    const int wid = tid >> 5;
    if ((tid & 31) == 0) {
#pragma unroll
        for (int d = 0; d < 8; d++) wpart[wid][d] = p[d];
    }
    __syncthreads();
    if (tid < 8) {
        float s = 0.f;
#pragma unroll
        for (int w = 0; w < 16; w++) s += wpart[w][tid];
        g_h0p[b][jc][tid] = s;
    }
}

// =====================================================================
// K5: elu(h0) -> concat with feats -> lin1 -> prelu -> bn(affine) -> lin2
// grid 1, 256 threads: thread = (b, k)
// =====================================================================
__global__ __launch_bounds__(256) void k5_mlp(const float* __restrict__ feats,
                                              const float* __restrict__ lin1w,
                                              const float* __restrict__ lin1b,
                                              const float* __restrict__ prelua,
                                              const float* __restrict__ gamma,
                                              const float* __restrict__ beta,
                                              const float* __restrict__ lin2w,
                                              const float* __restrict__ lin2b,
                                              float* __restrict__ out) {
    const int tid = threadIdx.x;
    const int b = tid >> 3, k = tid & 7;

    float gat[8];
#pragma unroll
    for (int d = 0; d < 8; d++) {
        float v = g_h0p[b][0][d] + g_h0p[b][1][d] + g_h0p[b][2][d] + g_h0p[b][3][d];
        gat[d] = eluf(v);
    }

    const float* w = lin1w + k * 136;
    const float* fr = feats + b * 128;
    float z = lin1b[k];
#pragma unroll 8
    for (int f = 0; f < 128; f++) z += fr[f] * w[f];
#pragma unroll
    for (int d = 0; d < 8; d++) z += gat[d] * w[128 + d];

    const float pa = prelua[0];
    z = (z >= 0.f) ? z : pa * z;
    z = z * rsqrtf(1.0f + 1e-5f) * gamma[k] + beta[k];

    float v = z * lin2w[k];
    v += __shfl_xor_sync(0xffffffffu, v, 4);
    v += __shfl_xor_sync(0xffffffffu, v, 2);
    v += __shfl_xor_sync(0xffffffffu, v, 1);
    if (k == 0) out[b] = v + lin2b[0];
}

// =====================================================================
extern "C" void kernel_launch(void* const* d_in, const int* in_sizes, int n_in,
                              void* d_out, int out_size) {
    (void)in_sizes; (void)n_in; (void)out_size;
    const float* feats  = (const float*)d_in[0];
    const float* nf     = (const float*)d_in[1];
    const float* Ws     = (const float*)d_in[2];
    const float* As     = (const float*)d_in[3];
    const float* Wout   = (const float*)d_in[4];
    const float* aout   = (const float*)d_in[5];
    const float* lin1w  = (const float*)d_in[6];
    const float* lin1b  = (const float*)d_in[7];
    const float* prelua = (const float*)d_in[8];
    const float* gamma  = (const float*)d_in[9];
    const float* beta   = (const float*)d_in[10];
    const float* lin2w  = (const float*)d_in[11];
    const float* lin2b  = (const float*)d_in[12];
    float* out = (float*)d_out;

    k1_proj<<<dim3(32, 4), 256>>>(nf, Ws);
    k2_att1<<<dim3(32, 8), 512>>>(As);
    k3_proj2<<<dim3(32, 2), 256>>>(Wout, aout);
    k4_att2<<<dim3(32, 4), 512>>>();
    k5_mlp<<<1, 256>>>(feats, lin1w, lin1b, prelua, gamma, beta, lin2w, lin2b, out);
}

// round 2
// speedup vs baseline: 1.7582x; 1.7582x over previous
#include <cuda_runtime.h>

typedef unsigned long long ull;

#define LOG2E 1.4426950408889634f
#define BB 32
#define NN 512
#define NH 8
#define ND 8
#define NF 128

// ---------------- scratch (static device globals; no allocation) ----------------
__device__ float g_Wh1[BB * NH * NN * ND];   // layer-1 projected features, [b][h][n][d]
__device__ float g_x[BB * NN * NH * ND];     // layer-1 output (concat heads), [b][n][h*8+d]

// ---------------- helpers ----------------
__device__ __forceinline__ float ex2f(float x) {
    float r; asm("ex2.approx.f32 %0, %1;" : "=f"(r) : "f"(x)); return r;
}
__device__ __forceinline__ void ffma2(ull &acc, ull a, ull b) {
    asm("fma.rn.f32x2 %0, %1, %2, %0;" : "+l"(acc) : "l"(a), "l"(b));
}
__device__ __forceinline__ ull pack2(float x) {
    ull r; asm("mov.b64 %0, {%1, %1};" : "=l"(r) : "f"(x)); return r;
}
__device__ __forceinline__ float lrelu02(float x) { return fmaxf(x, 0.2f * x); }
__device__ __forceinline__ float eluf(float x) { return x > 0.f ? x : expm1f(x); }

// monotone float -> sortable u32
__device__ __forceinline__ unsigned f2s(float f) {
    unsigned u = __float_as_uint(f);
    return u ^ ((u & 0x80000000u) ? 0xFFFFFFFFu : 0x80000000u);
}

// =====================================================================
// K1: Wh1[b,h,n,d] = sum_f nf[b,n,f] * Ws[h,f,d]
// grid (32, 4), 256 threads: 128 n-rows per block, 2 threads per row
// =====================================================================
__global__ __launch_bounds__(256) void k1_proj(const float* __restrict__ nf,
                                               const float* __restrict__ Ws) {
    __shared__ ull Wsm[128][32];
    const int b = blockIdx.x, tid = threadIdx.x;
    float* Wf = reinterpret_cast<float*>(Wsm);
    for (int idx = tid; idx < 128 * 64; idx += 256) {
        int f = idx >> 6, c = idx & 63;
        Wf[idx] = Ws[((c >> 3) * 128 + f) * 8 + (c & 7)];
    }
    __syncthreads();

    const int nl = tid & 127, q = tid >> 7;
    const int n = blockIdx.y * 128 + nl;
    const float4* row = reinterpret_cast<const float4*>(nf + (b * NN + n) * NF);

    ull acc[16];
#pragma unroll
    for (int k = 0; k < 16; k++) acc[k] = 0ull;

#pragma unroll 4
    for (int f4 = 0; f4 < 32; f4++) {
        float4 v = row[f4];
        float vs[4] = {v.x, v.y, v.z, v.w};
#pragma unroll
        for (int u = 0; u < 4; u++) {
            ull p = pack2(vs[u]);
            const ull* wrow = &Wsm[f4 * 4 + u][q * 16];
#pragma unroll
            for (int k = 0; k < 16; k++) ffma2(acc[k], p, wrow[k]);
        }
    }

    ull* out = reinterpret_cast<ull*>(g_Wh1);
#pragma unroll
    for (int k = 0; k < 16; k++) {
        int c0 = q * 32 + 2 * k;
        int h = c0 >> 3, d = c0 & 7;
        out[((size_t)(b * NH + h) * NN + n) * 4 + (d >> 1)] = acc[k];
    }
}

// =====================================================================
// K2: layer-1 attention via branch-factorized softmax + sort/prefix-sum.
// e_ij = exp(lrelu(s1_i+s2_j)) = [t>=0] E1_i E2_j + [t<0] F1_i F2_j
// grid (32, 8), 512 threads, dynamic smem
// =====================================================================
struct K2S {
    ull sortA[NN];          // key = sortable(s1L) << 32 | i
    ull sortB[NN];          // key = sortable(s2L) << 32 | j
    float SU[NN][9];        // (later) inclusive prefix of U in sorted-s2 order
    float SV[NN][9];        // inclusive prefix of V in sorted-s2 order
    float E1s[NN];
    float F1s[NN];
    float PE[NN];           // inclusive prefix of E1 in sorted-s1 order
    float PF[NN];           // inclusive prefix of F1 in sorted-s1 order
    float warpbuf[16 * 8];
    float redbuf[16];
    unsigned short rankB[NN];
};

__device__ __forceinline__ void scan2_inplace(float* A, float* B, float* warpbuf, int tid) {
    const int lane = tid & 31, wid = tid >> 5;
    float a = A[tid], b = B[tid];
#pragma unroll
    for (int s = 1; s < 32; s <<= 1) {
        float ta = __shfl_up_sync(0xffffffffu, a, s);
        float tb = __shfl_up_sync(0xffffffffu, b, s);
        if (lane >= s) { a += ta; b += tb; }
    }
    if (lane == 31) { warpbuf[wid] = a; warpbuf[16 + wid] = b; }
    __syncthreads();
    float oa = 0.f, ob = 0.f;
#pragma unroll
    for (int w = 0; w < 16; w++)
        if (w < wid) { oa += warpbuf[w]; ob += warpbuf[16 + w]; }
    A[tid] = a + oa;
    B[tid] = b + ob;
    __syncthreads();
}

__device__ __forceinline__ void scan8_inplace(float (*A)[9], float* warpbuf, int tid) {
    const int lane = tid & 31, wid = tid >> 5;
    float v[8];
#pragma unroll
    for (int d = 0; d < 8; d++) v[d] = A[tid][d];
#pragma unroll
    for (int s = 1; s < 32; s <<= 1) {
#pragma unroll
        for (int d = 0; d < 8; d++) {
            float t = __shfl_up_sync(0xffffffffu, v[d], s);
            if (lane >= s) v[d] += t;
        }
    }
    if (lane == 31) {
#pragma unroll
        for (int d = 0; d < 8; d++) warpbuf[wid * 8 + d] = v[d];
    }
    __syncthreads();
    float off[8] = {0, 0, 0, 0, 0, 0, 0, 0};
    for (int w = 0; w < 16; w++) {
        if (w < wid) {
#pragma unroll
            for (int d = 0; d < 8; d++) off[d] += warpbuf[w * 8 + d];
        }
    }
#pragma unroll
    for (int d = 0; d < 8; d++) A[tid][d] = v[d] + off[d];
    __syncthreads();
}

__device__ __forceinline__ int lower_bound512(const ull* arr, ull X) {
    int c = 0;
#pragma unroll
    for (int s = 256; s >= 1; s >>= 1) {
        int t = c + s;
        if (t <= NN && arr[t - 1] < X) c = t;
    }
    return c;
}

__global__ __launch_bounds__(512) void k2_att1(const float* __restrict__ As) {
    extern __shared__ char raw[];
    K2S& S = *reinterpret_cast<K2S*>(raw);
    const int b = blockIdx.x, h = blockIdx.y, tid = threadIdx.x;

    const float* wg = g_Wh1 + (size_t)(b * NH + h) * NN * ND;
    float4 w0 = reinterpret_cast<const float4*>(wg)[tid * 2];
    float4 w1 = reinterpret_cast<const float4*>(wg)[tid * 2 + 1];

    const float* a = As + h * 16;
    float s1 = w0.x * a[0] + w0.y * a[1] + w0.z * a[2] + w0.w * a[3]
             + w1.x * a[4] + w1.y * a[5] + w1.z * a[6] + w1.w * a[7];
    float s2 = w0.x * a[8] + w0.y * a[9] + w0.z * a[10] + w0.w * a[11]
             + w1.x * a[12] + w1.y * a[13] + w1.z * a[14] + w1.w * a[15];
    const float s1L = s1 * LOG2E, s2L = s2 * LOG2E;

    // block max M of s1L
    float m = s1L;
#pragma unroll
    for (int o = 16; o >= 1; o >>= 1) m = fmaxf(m, __shfl_xor_sync(0xffffffffu, m, o));
    if ((tid & 31) == 0) S.redbuf[tid >> 5] = m;
    __syncthreads();
    float M = S.redbuf[0];
#pragma unroll
    for (int w = 1; w < 16; w++) M = fmaxf(M, S.redbuf[w]);

    const float E1 = ex2f(s1L - M);
    const float F1 = ex2f(0.2f * (s1L - M));
    S.E1s[tid] = E1;
    S.F1s[tid] = F1;
    S.sortA[tid] = (((ull)f2s(s1L)) << 32) | (unsigned)tid;
    S.sortB[tid] = (((ull)f2s(s2L)) << 32) | (unsigned)tid;
    __syncthreads();

    // interleaved bitonic sorts of s1-keys and s2-keys (ascending)
    for (int k = 2; k <= NN; k <<= 1) {
        for (int s = k >> 1; s >= 1; s >>= 1) {
            ull a0 = S.sortA[tid], b0 = S.sortA[tid ^ s];
            ull a1 = S.sortB[tid], b1 = S.sortB[tid ^ s];
            bool up = ((tid & k) == 0);
            bool low = ((tid & s) == 0);
            bool keepmin = (low == up);
            ull r0 = ((a0 < b0) == keepmin) ? a0 : b0;
            ull r1 = ((a1 < b1) == keepmin) ? a1 : b1;
            __syncthreads();
            S.sortA[tid] = r0;
            S.sortB[tid] = r1;
            __syncthreads();
        }
    }

    // inverse perm of sortB; gather E1/F1 into sorted-s1 order
    {
        int ja = (int)(S.sortA[tid] & 0xffffffffu);
        int jb = (int)(S.sortB[tid] & 0xffffffffu);
        S.rankB[jb] = (unsigned short)tid;
        S.PE[tid] = S.E1s[ja];
        S.PF[tid] = S.F1s[ja];
    }
    __syncthreads();
    scan2_inplace(S.PE, S.PF, S.warpbuf, tid);
    const float TE = S.PE[NN - 1];

    // per thread j = tid: Z_j, then scatter U_j, V_j into sorted-s2 slots
    const int c = lower_bound512(S.sortA, ((ull)f2s(-s2L)) << 32);
    const float sumEge = TE - (c > 0 ? S.PE[c - 1] : 0.f);
    const float preF   = (c > 0 ? S.PF[c - 1] : 0.f);
    const float mj = lrelu02(M + s2L);
    const float E2 = ex2f(s2L + M - mj);
    const float F2 = ex2f(0.2f * (s2L + M) - mj);
    const float rz = 1.0f / (E2 * sumEge + F2 * preF);
    const float ue = E2 * rz, vf = F2 * rz;

    const float wv[8] = {w0.x, w0.y, w0.z, w0.w, w1.x, w1.y, w1.z, w1.w};
    const int r = S.rankB[tid];
#pragma unroll
    for (int d = 0; d < 8; d++) {
        S.SU[r][d] = ue * wv[d];
        S.SV[r][d] = vf * wv[d];
    }
    __syncthreads();
    scan8_inplace(S.SU, S.warpbuf, tid);
    scan8_inplace(S.SV, S.warpbuf, tid);

    float TU[8];
#pragma unroll
    for (int d = 0; d < 8; d++) TU[d] = S.SU[NN - 1][d];

    // per thread i = tid: h_i = E1*SufU(c2) + F1*PreV(c2), then elu
    const int c2 = lower_bound512(S.sortB, ((ull)f2s(-s1L)) << 32);
    float res[8];
#pragma unroll
    for (int d = 0; d < 8; d++) {
        float su = TU[d] - (c2 > 0 ? S.SU[c2 - 1][d] : 0.f);
        float pv = (c2 > 0 ? S.SV[c2 - 1][d] : 0.f);
        res[d] = eluf(E1 * su + F1 * pv);
    }
    float4* xo = reinterpret_cast<float4*>(g_x + (size_t)(b * NN + tid) * (NH * ND) + h * ND);
    xo[0] = make_float4(res[0], res[1], res[2], res[3]);
    xo[1] = make_float4(res[4], res[5], res[6], res[7]);
}

// =====================================================================
// K34: merged layer-2 projection + attention (row 0) + MLP head.
// grid 32 (one block per batch), 512 threads.
// =====================================================================
__global__ __launch_bounds__(512) void k34(const float* __restrict__ Wout,
                                           const float* __restrict__ aout,
                                           const float* __restrict__ feats,
                                           const float* __restrict__ lin1w,
                                           const float* __restrict__ lin1b,
                                           const float* __restrict__ prelua,
                                           const float* __restrict__ gamma,
                                           const float* __restrict__ beta,
                                           const float* __restrict__ lin2w,
                                           const float* __restrict__ lin2b,
                                           float* __restrict__ out) {
    __shared__ float Wo[64 * 8];
    __shared__ float ao[16];
    __shared__ ull sortA[NN];
    __shared__ float E1s[NN], F1s[NN], PE[NN], PF[NN];
    __shared__ float warpbuf[32];
    __shared__ float redbuf[16];
    __shared__ float wpart[16][8];
    __shared__ float hsum[8];
    __shared__ float bc0[1];

    const int b = blockIdx.x, tid = threadIdx.x;
    const int lane = tid & 31, wid = tid >> 5;

    for (int idx = tid; idx < 512; idx += 512) Wo[idx] = Wout[idx];
    if (tid < 16) ao[tid] = aout[tid];
    __syncthreads();

    // projection: wh2[d] = x[b,tid,:] @ Wout
    const float4* row = reinterpret_cast<const float4*>(g_x + (size_t)(b * NN + tid) * 64);
    float acc[8] = {0, 0, 0, 0, 0, 0, 0, 0};
#pragma unroll 4
    for (int f4 = 0; f4 < 16; f4++) {
        float4 v = row[f4];
        float vs[4] = {v.x, v.y, v.z, v.w};
#pragma unroll
        for (int u = 0; u < 4; u++) {
            const float* wr = &Wo[(f4 * 4 + u) * 8];
#pragma unroll
            for (int d = 0; d < 8; d++) acc[d] += vs[u] * wr[d];
        }
    }
    float s1 = 0.f, s2 = 0.f;
#pragma unroll
    for (int d = 0; d < 8; d++) { s1 += acc[d] * ao[d]; s2 += acc[d] * ao[8 + d]; }
    const float s1L = s1 * LOG2E, s2L = s2 * LOG2E;

    // block max M of s1L
    float m = s1L;
#pragma unroll
    for (int o = 16; o >= 1; o >>= 1) m = fmaxf(m, __shfl_xor_sync(0xffffffffu, m, o));
    if (lane == 0) redbuf[wid] = m;
    __syncthreads();
    float M = redbuf[0];
#pragma unroll
    for (int w = 1; w < 16; w++) M = fmaxf(M, redbuf[w]);

    const float E1 = ex2f(s1L - M);
    const float F1 = ex2f(0.2f * (s1L - M));
    E1s[tid] = E1;
    F1s[tid] = F1;
    sortA[tid] = (((ull)f2s(s1L)) << 32) | (unsigned)tid;
    if (tid == 0) bc0[0] = s1L;
    __syncthreads();

    for (int k = 2; k <= NN; k <<= 1) {
        for (int s = k >> 1; s >= 1; s >>= 1) {
            ull a0 = sortA[tid], b0 = sortA[tid ^ s];
            bool up = ((tid & k) == 0);
            bool low = ((tid & s) == 0);
            bool keepmin = (low == up);
            ull r0 = ((a0 < b0) == keepmin) ? a0 : b0;
            __syncthreads();
            sortA[tid] = r0;
            __syncthreads();
        }
    }
    {
        int ja = (int)(sortA[tid] & 0xffffffffu);
        PE[tid] = E1s[ja];
        PF[tid] = F1s[ja];
    }
    __syncthreads();
    scan2_inplace(PE, PF, warpbuf, tid);
    const float TE = PE[NN - 1];

    // per thread j: weight of node 0 attending to j, times wh2_j
    const int c = lower_bound512(sortA, ((ull)f2s(-s2L)) << 32);
    const float sumEge = TE - (c > 0 ? PE[c - 1] : 0.f);
    const float preF   = (c > 0 ? PF[c - 1] : 0.f);
    const float mj = lrelu02(M + s2L);
    const float E2 = ex2f(s2L + M - mj);
    const float F2 = ex2f(0.2f * (s2L + M) - mj);
    const float Z = E2 * sumEge + F2 * preF;

    const float s1L0 = bc0[0];
    const float t0 = s1L0 + s2L;
    const float E10 = ex2f(s1L0 - M), F10 = ex2f(0.2f * (s1L0 - M));
    const float e0 = (t0 >= 0.f) ? E10 * E2 : F10 * F2;
    const float wj = e0 / Z;

    float p[8];
#pragma unroll
    for (int d = 0; d < 8; d++) p[d] = wj * acc[d];
#pragma unroll
    for (int d = 0; d < 8; d++) {
#pragma unroll
        for (int o = 16; o >= 1; o >>= 1) p[d] += __shfl_xor_sync(0xffffffffu, p[d], o);
    }
    if (lane == 0) {
#pragma unroll
        for (int d = 0; d < 8; d++) wpart[wid][d] = p[d];
    }
    __syncthreads();
    if (tid < 8) {
        float s = 0.f;
#pragma unroll
        for (int w = 0; w < 16; w++) s += wpart[w][tid];
        hsum[tid] = eluf(s);
    }
    __syncthreads();

    // MLP head for this b (8 threads)
    if (tid < 8) {
        const int k = tid;
        const float* w = lin1w + k * 136;
        const float* fr = feats + b * 128;
        float z = lin1b[k];
#pragma unroll 8
        for (int f = 0; f < 128; f++) z += fr[f] * w[f];
#pragma unroll
        for (int d = 0; d < 8; d++) z += hsum[d] * w[128 + d];
        const float pa = prelua[0];
        z = (z >= 0.f) ? z : pa * z;
        z = z * rsqrtf(1.0f + 1e-5f) * gamma[k] + beta[k];
        float v = z * lin2w[k];
        v += __shfl_xor_sync(0x000000ffu, v, 4);
        v += __shfl_xor_sync(0x000000ffu, v, 2);
        v += __shfl_xor_sync(0x000000ffu, v, 1);
        if (k == 0) out[b] = v + lin2b[0];
    }
}

// =====================================================================
extern "C" void kernel_launch(void* const* d_in, const int* in_sizes, int n_in,
                              void* d_out, int out_size) {
    (void)in_sizes; (void)n_in; (void)out_size;
    const float* feats  = (const float*)d_in[0];
    const float* nf     = (const float*)d_in[1];
    const float* Ws     = (const float*)d_in[2];
    const float* As     = (const float*)d_in[3];
    const float* Wout   = (const float*)d_in[4];
    const float* aout   = (const float*)d_in[5];
    const float* lin1w  = (const float*)d_in[6];
    const float* lin1b  = (const float*)d_in[7];
    const float* prelua = (const float*)d_in[8];
    const float* gamma  = (const float*)d_in[9];
    const float* beta   = (const float*)d_in[10];
    const float* lin2w  = (const float*)d_in[11];
    const float* lin2b  = (const float*)d_in[12];
    float* out = (float*)d_out;

    static bool attr_done = false;
    if (!attr_done) {
        cudaFuncSetAttribute(k2_att1, cudaFuncAttributeMaxDynamicSharedMemorySize,
                             (int)sizeof(K2S));
        attr_done = true;
    }

    k1_proj<<<dim3(32, 4), 256>>>(nf, Ws);
    k2_att1<<<dim3(32, 8), 512, sizeof(K2S)>>>(As);
    k34<<<32, 512>>>(Wout, aout, feats, lin1w, lin1b, prelua, gamma, beta,
                     lin2w, lin2b, out);
}

// round 3
// speedup vs baseline: 1.7600x; 1.0010x over previous
#include <cuda_runtime.h>

typedef unsigned long long ull;

#define LOG2E 1.4426950408889634f
#define BB 32
#define NN 512
#define NH 8
#define ND 8
#define NF 128

// ---------------- scratch ----------------
__device__ float g_x[BB * NN * NH * ND];     // layer-1 output (concat heads), [b][n][h*8+d]

// ---------------- helpers ----------------
__device__ __forceinline__ float ex2f(float x) {
    float r; asm("ex2.approx.f32 %0, %1;" : "=f"(r) : "f"(x)); return r;
}
__device__ __forceinline__ void ffma2(ull &acc, ull a, ull b) {
    asm("fma.rn.f32x2 %0, %1, %2, %0;" : "+l"(acc) : "l"(a), "l"(b));
}
__device__ __forceinline__ ull pack2(float x) {
    ull r; asm("mov.b64 %0, {%1, %1};" : "=l"(r) : "f"(x)); return r;
}
__device__ __forceinline__ float lrelu02(float x) { return fmaxf(x, 0.2f * x); }
__device__ __forceinline__ float eluf(float x) { return x > 0.f ? x : expm1f(x); }

// monotone float -> sortable u32
__device__ __forceinline__ unsigned f2s(float f) {
    unsigned u = __float_as_uint(f);
    return u ^ ((u & 0x80000000u) ? 0xFFFFFFFFu : 0x80000000u);
}

__device__ __forceinline__ int lower_bound512(const ull* arr, ull X) {
    int c = 0;
#pragma unroll
    for (int s = 256; s >= 1; s >>= 1) {
        int t = c + s;
        if (t <= NN && arr[t - 1] < X) c = t;
    }
    return c;
}

// =====================================================================
// K2: fused projection + layer-1 attention (branch-factorized softmax).
// grid (32, 8), 512 threads, dynamic smem, 2 blocks/SM.
// =====================================================================
struct K2S {
    ull sortA[NN];          // sorted keys of s1L (key<<32 | i), used for search
    ull sortB[NN];          // sorted keys of s2L
    float SU[NN][9];        // inclusive prefix of U in sorted-s2 order
    float SV[NN][9];
    float E1s[NN];
    float F1s[NN];
    float PE[NN];           // inclusive prefix of E1 in sorted-s1 order
    float PF[NN];
    float warpbuf[16 * 8];
    float redbuf[16];
    unsigned short rankB[NN];
    ull Wsm[128][4];        // W_h packed as f32x2 pairs: [f][(d0,d1)..(d6,d7)]
};

__device__ __forceinline__ void scan2_inplace(float* A, float* B, float* warpbuf, int tid) {
    const int lane = tid & 31, wid = tid >> 5;
    float a = A[tid], b = B[tid];
#pragma unroll
    for (int s = 1; s < 32; s <<= 1) {
        float ta = __shfl_up_sync(0xffffffffu, a, s);
        float tb = __shfl_up_sync(0xffffffffu, b, s);
        if (lane >= s) { a += ta; b += tb; }
    }
    if (lane == 31) { warpbuf[wid] = a; warpbuf[16 + wid] = b; }
    __syncthreads();
    float oa = 0.f, ob = 0.f;
#pragma unroll
    for (int w = 0; w < 16; w++)
        if (w < wid) { oa += warpbuf[w]; ob += warpbuf[16 + w]; }
    A[tid] = a + oa;
    B[tid] = b + ob;
    __syncthreads();
}

__device__ __forceinline__ void scan8_inplace(float (*A)[9], float* warpbuf, int tid) {
    const int lane = tid & 31, wid = tid >> 5;
    float v[8];
#pragma unroll
    for (int d = 0; d < 8; d++) v[d] = A[tid][d];
#pragma unroll
    for (int s = 1; s < 32; s <<= 1) {
#pragma unroll
        for (int d = 0; d < 8; d++) {
            float t = __shfl_up_sync(0xffffffffu, v[d], s);
            if (lane >= s) v[d] += t;
        }
    }
    if (lane == 31) {
#pragma unroll
        for (int d = 0; d < 8; d++) warpbuf[wid * 8 + d] = v[d];
    }
    __syncthreads();
    float off[8] = {0, 0, 0, 0, 0, 0, 0, 0};
    for (int w = 0; w < 16; w++) {
        if (w < wid) {
#pragma unroll
            for (int d = 0; d < 8; d++) off[d] += warpbuf[w * 8 + d];
        }
    }
#pragma unroll
    for (int d = 0; d < 8; d++) A[tid][d] = v[d] + off[d];
    __syncthreads();
}

__global__ __launch_bounds__(512, 2) void k2_att1(const float* __restrict__ nf,
                                                  const float* __restrict__ Ws,
                                                  const float* __restrict__ As) {
    extern __shared__ char raw[];
    K2S& S = *reinterpret_cast<K2S*>(raw);
    const int b = blockIdx.x, h = blockIdx.y, tid = threadIdx.x;

    // ---- load W_h into shared (1024 floats) ----
    {
        float* Wf = reinterpret_cast<float*>(S.Wsm);
        const float* wsrc = Ws + h * (NF * ND);
        Wf[tid] = wsrc[tid];
        Wf[tid + 512] = wsrc[tid + 512];
    }
    __syncthreads();

    // ---- projection: wh[0..7] = nf[b, tid, :] @ W_h ----
    const float4* row = reinterpret_cast<const float4*>(nf + (size_t)(b * NN + tid) * NF);
    ull acc[4] = {0, 0, 0, 0};
#pragma unroll 4
    for (int f4 = 0; f4 < 32; f4++) {
        float4 v = row[f4];
        float vs[4] = {v.x, v.y, v.z, v.w};
#pragma unroll
        for (int u = 0; u < 4; u++) {
            ull p = pack2(vs[u]);
            const ull* wr = S.Wsm[f4 * 4 + u];
            ffma2(acc[0], p, wr[0]);
            ffma2(acc[1], p, wr[1]);
            ffma2(acc[2], p, wr[2]);
            ffma2(acc[3], p, wr[3]);
        }
    }
    float wv[8];
#pragma unroll
    for (int k = 0; k < 4; k++) {
        wv[2 * k]     = __uint_as_float((unsigned)(acc[k] & 0xffffffffu));
        wv[2 * k + 1] = __uint_as_float((unsigned)(acc[k] >> 32));
    }

    const float* a = As + h * 16;
    float s1 = 0.f, s2 = 0.f;
#pragma unroll
    for (int d = 0; d < 8; d++) { s1 += wv[d] * a[d]; s2 += wv[d] * a[8 + d]; }
    const float s1L = s1 * LOG2E, s2L = s2 * LOG2E;

    // ---- block max M of s1L ----
    float m = s1L;
#pragma unroll
    for (int o = 16; o >= 1; o >>= 1) m = fmaxf(m, __shfl_xor_sync(0xffffffffu, m, o));
    if ((tid & 31) == 0) S.redbuf[tid >> 5] = m;
    __syncthreads();
    float M = S.redbuf[0];
#pragma unroll
    for (int w = 1; w < 16; w++) M = fmaxf(M, S.redbuf[w]);

    const float E1 = ex2f(s1L - M);
    const float F1 = ex2f(0.2f * (s1L - M));
    S.E1s[tid] = E1;
    S.F1s[tid] = F1;

    // ---- register-resident bitonic sort of both key sets ----
    ull va = (((ull)f2s(s1L)) << 32) | (unsigned)tid;
    ull vb = (((ull)f2s(s2L)) << 32) | (unsigned)tid;
    for (int k = 2; k <= NN; k <<= 1) {
        for (int s = k >> 1; s >= 1; s >>= 1) {
            const bool up = ((tid & k) == 0);
            const bool low = ((tid & s) == 0);
            const bool keepmin = (low == up);
            ull oa, ob;
            if (s >= 32) {
                S.sortA[tid] = va; S.sortB[tid] = vb;
                __syncthreads();
                oa = S.sortA[tid ^ s]; ob = S.sortB[tid ^ s];
                __syncthreads();
            } else {
                oa = __shfl_xor_sync(0xffffffffu, va, s);
                ob = __shfl_xor_sync(0xffffffffu, vb, s);
            }
            va = ((va < oa) == keepmin) ? va : oa;
            vb = ((vb < ob) == keepmin) ? vb : ob;
        }
    }
    S.sortA[tid] = va;
    S.sortB[tid] = vb;
    // gather E1/F1 into sorted-s1 order; build inverse perm of sortB
    {
        int ja = (int)(va & 0xffffffffu);
        int jb = (int)(vb & 0xffffffffu);
        S.rankB[jb] = (unsigned short)tid;
        S.PE[tid] = S.E1s[ja];     // E1s written pre-sort; sort barriers order it
        S.PF[tid] = S.F1s[ja];
    }
    __syncthreads();
    scan2_inplace(S.PE, S.PF, S.warpbuf, tid);
    const float TE = S.PE[NN - 1];

    // ---- per thread j: Z_j, scatter U_j, V_j into sorted-s2 slots ----
    const int c = lower_bound512(S.sortA, ((ull)f2s(-s2L)) << 32);
    const float sumEge = TE - (c > 0 ? S.PE[c - 1] : 0.f);
    const float preF   = (c > 0 ? S.PF[c - 1] : 0.f);
    const float mj = lrelu02(M + s2L);
    const float E2 = ex2f(s2L + M - mj);
    const float F2 = ex2f(0.2f * (s2L + M) - mj);
    const float rz = 1.0f / (E2 * sumEge + F2 * preF);
    const float ue = E2 * rz, vf = F2 * rz;

    const int r = S.rankB[tid];
#pragma unroll
    for (int d = 0; d < 8; d++) {
        S.SU[r][d] = ue * wv[d];
        S.SV[r][d] = vf * wv[d];
    }
    __syncthreads();
    scan8_inplace(S.SU, S.warpbuf, tid);
    scan8_inplace(S.SV, S.warpbuf, tid);

    float TU[8];
#pragma unroll
    for (int d = 0; d < 8; d++) TU[d] = S.SU[NN - 1][d];

    // ---- per thread i: h_i = E1*SufU + F1*PreV, elu, store ----
    const int c2 = lower_bound512(S.sortB, ((ull)f2s(-s1L)) << 32);
    float res[8];
#pragma unroll
    for (int d = 0; d < 8; d++) {
        float su = TU[d] - (c2 > 0 ? S.SU[c2 - 1][d] : 0.f);
        float pv = (c2 > 0 ? S.SV[c2 - 1][d] : 0.f);
        res[d] = eluf(E1 * su + F1 * pv);
    }
    float4* xo = reinterpret_cast<float4*>(g_x + (size_t)(b * NN + tid) * (NH * ND) + h * ND);
    xo[0] = make_float4(res[0], res[1], res[2], res[3]);
    xo[1] = make_float4(res[4], res[5], res[6], res[7]);
}

// =====================================================================
// K34: merged layer-2 projection + attention (row 0) + MLP head.
// grid 32 (one block per batch), 512 threads.
// =====================================================================
__global__ __launch_bounds__(512) void k34(const float* __restrict__ Wout,
                                           const float* __restrict__ aout,
                                           const float* __restrict__ feats,
                                           const float* __restrict__ lin1w,
                                           const float* __restrict__ lin1b,
                                           const float* __restrict__ prelua,
                                           const float* __restrict__ gamma,
                                           const float* __restrict__ beta,
                                           const float* __restrict__ lin2w,
                                           const float* __restrict__ lin2b,
                                           float* __restrict__ out) {
    __shared__ float Wo[64 * 8];
    __shared__ float ao[16];
    __shared__ ull sortA[NN];
    __shared__ float E1s[NN], F1s[NN], PE[NN], PF[NN];
    __shared__ float warpbuf[32];
    __shared__ float redbuf[16];
    __shared__ float wpart[16][8];
    __shared__ float hsum[8];
    __shared__ float bc0[1];

    const int b = blockIdx.x, tid = threadIdx.x;
    const int lane = tid & 31, wid = tid >> 5;

    if (tid < 512) Wo[tid] = Wout[tid];
    if (tid < 16) ao[tid] = aout[tid];
    __syncthreads();

    // projection: wh2[d] = x[b,tid,:] @ Wout
    const float4* row = reinterpret_cast<const float4*>(g_x + (size_t)(b * NN + tid) * 64);
    float acc[8] = {0, 0, 0, 0, 0, 0, 0, 0};
#pragma unroll 4
    for (int f4 = 0; f4 < 16; f4++) {
        float4 v = row[f4];
        float vs[4] = {v.x, v.y, v.z, v.w};
#pragma unroll
        for (int u = 0; u < 4; u++) {
            const float* wr = &Wo[(f4 * 4 + u) * 8];
#pragma unroll
            for (int d = 0; d < 8; d++) acc[d] += vs[u] * wr[d];
        }
    }
    float s1 = 0.f, s2 = 0.f;
#pragma unroll
    for (int d = 0; d < 8; d++) { s1 += acc[d] * ao[d]; s2 += acc[d] * ao[8 + d]; }
    const float s1L = s1 * LOG2E, s2L = s2 * LOG2E;

    float m = s1L;
#pragma unroll
    for (int o = 16; o >= 1; o >>= 1) m = fmaxf(m, __shfl_xor_sync(0xffffffffu, m, o));
    if (lane == 0) redbuf[wid] = m;
    __syncthreads();
    float M = redbuf[0];
#pragma unroll
    for (int w = 1; w < 16; w++) M = fmaxf(M, redbuf[w]);

    const float E1 = ex2f(s1L - M);
    const float F1 = ex2f(0.2f * (s1L - M));
    E1s[tid] = E1;
    F1s[tid] = F1;
    if (tid == 0) bc0[0] = s1L;

    // register-resident bitonic sort of s1 keys
    ull va = (((ull)f2s(s1L)) << 32) | (unsigned)tid;
    for (int k = 2; k <= NN; k <<= 1) {
        for (int s = k >> 1; s >= 1; s >>= 1) {
            const bool up = ((tid & k) == 0);
            const bool low = ((tid & s) == 0);
            const bool keepmin = (low == up);
            ull oa;
            if (s >= 32) {
                sortA[tid] = va;
                __syncthreads();
                oa = sortA[tid ^ s];
                __syncthreads();
            } else {
                oa = __shfl_xor_sync(0xffffffffu, va, s);
            }
            va = ((va < oa) == keepmin) ? va : oa;
        }
    }
    sortA[tid] = va;
    {
        int ja = (int)(va & 0xffffffffu);
        PE[tid] = E1s[ja];
        PF[tid] = F1s[ja];
    }
    __syncthreads();
    scan2_inplace(PE, PF, warpbuf, tid);
    const float TE = PE[NN - 1];

    // per thread j: weight of node 0 attending to j, times wh2_j
    const int c = lower_bound512(sortA, ((ull)f2s(-s2L)) << 32);
    const float sumEge = TE - (c > 0 ? PE[c - 1] : 0.f);
    const float preF   = (c > 0 ? PF[c - 1] : 0.f);
    const float mj = lrelu02(M + s2L);
    const float E2 = ex2f(s2L + M - mj);
    const float F2 = ex2f(0.2f * (s2L + M) - mj);
    const float Z = E2 * sumEge + F2 * preF;

    const float s1L0 = bc0[0];
    const float t0 = s1L0 + s2L;
    const float E10 = ex2f(s1L0 - M), F10 = ex2f(0.2f * (s1L0 - M));
    const float e0 = (t0 >= 0.f) ? E10 * E2 : F10 * F2;
    const float wj = e0 / Z;

    float p[8];
#pragma unroll
    for (int d = 0; d < 8; d++) p[d] = wj * acc[d];
#pragma unroll
    for (int d = 0; d < 8; d++) {
#pragma unroll
        for (int o = 16; o >= 1; o >>= 1) p[d] += __shfl_xor_sync(0xffffffffu, p[d], o);
    }
    if (lane == 0) {
#pragma unroll
        for (int d = 0; d < 8; d++) wpart[wid][d] = p[d];
    }
    __syncthreads();
    if (tid < 8) {
        float s = 0.f;
#pragma unroll
        for (int w = 0; w < 16; w++) s += wpart[w][tid];
        hsum[tid] = eluf(s);
    }
    __syncthreads();

    // MLP head for this b (8 threads)
    if (tid < 8) {
        const int k = tid;
        const float* w = lin1w + k * 136;
        const float* fr = feats + b * 128;
        float z = lin1b[k];
#pragma unroll 8
        for (int f = 0; f < 128; f++) z += fr[f] * w[f];
#pragma unroll
        for (int d = 0; d < 8; d++) z += hsum[d] * w[128 + d];
        const float pa = prelua[0];
        z = (z >= 0.f) ? z : pa * z;
        z = z * rsqrtf(1.0f + 1e-5f) * gamma[k] + beta[k];
        float v = z * lin2w[k];
        v += __shfl_xor_sync(0x000000ffu, v, 4);
        v += __shfl_xor_sync(0x000000ffu, v, 2);
        v += __shfl_xor_sync(0x000000ffu, v, 1);
        if (k == 0) out[b] = v + lin2b[0];
    }
}

// =====================================================================
extern "C" void kernel_launch(void* const* d_in, const int* in_sizes, int n_in,
                              void* d_out, int out_size) {
    (void)in_sizes; (void)n_in; (void)out_size;
    const float* feats  = (const float*)d_in[0];
    const float* nf     = (const float*)d_in[1];
    const float* Ws     = (const float*)d_in[2];
    const float* As     = (const float*)d_in[3];
    const float* Wout   = (const float*)d_in[4];
    const float* aout   = (const float*)d_in[5];
    const float* lin1w  = (const float*)d_in[6];
    const float* lin1b  = (const float*)d_in[7];
    const float* prelua = (const float*)d_in[8];
    const float* gamma  = (const float*)d_in[9];
    const float* beta   = (const float*)d_in[10];
    const float* lin2w  = (const float*)d_in[11];
    const float* lin2b  = (const float*)d_in[12];
    float* out = (float*)d_out;

    static bool attr_done = false;
    if (!attr_done) {
        cudaFuncSetAttribute(k2_att1, cudaFuncAttributeMaxDynamicSharedMemorySize,
                             (int)sizeof(K2S));
        attr_done = true;
    }

    k2_att1<<<dim3(32, 8), 512, sizeof(K2S)>>>(nf, Ws, As);
    k34<<<32, 512>>>(Wout, aout, feats, lin1w, lin1b, prelua, gamma, beta,
                     lin2w, lin2b, out);
}